// round 16
// baseline (speedup 1.0000x reference)
#include <cuda_runtime.h>
#include <cuda_fp16.h>
#include <math.h>
#include <stdint.h>

// Problem constants
#define BB 2
#define SS 2048
#define DD 2048
#define HH 16
#define DK 128
#define MM (BB*SS)          // 4096
#define KEY_SCALE 0.08838834764831843f  // 1/sqrt(128)

// -------------------- scratch (device globals; no allocations) --------------------
__device__ __half g_q[(size_t)BB*HH*SS*DK];   // [b,h,s,dk]
__device__ __half g_k[(size_t)BB*HH*SS*DK];   // [b,h,s,dk]
__device__ __half g_v[(size_t)BB*HH*SS*DK];   // [b,h,s,dk]
__device__ __half g_vt[(size_t)BB*HH*DK*SS];  // [b,h,dk,s]
__device__ float  g_gate[(size_t)BB*SS*HH];   // [b,s,h]
__device__ __half g_o[(size_t)BB*SS*DD];      // [b,s,h*dk]
__device__ __half g_xh[(size_t)MM*DD];        // states fp16
__device__ __half g_wq[(size_t)DD*DD];
__device__ __half g_wk[(size_t)DD*DD];
__device__ __half g_wv[(size_t)DD*DD];
__device__ __half g_wo[(size_t)DD*DD];

__device__ __forceinline__ void mma_f16(float* d, const uint32_t* a, const uint32_t* b) {
    asm volatile(
        "mma.sync.aligned.m16n8k16.row.col.f32.f16.f16.f32 "
        "{%0,%1,%2,%3}, {%4,%5,%6,%7}, {%8,%9}, {%0,%1,%2,%3};"
        : "+f"(d[0]), "+f"(d[1]), "+f"(d[2]), "+f"(d[3])
        : "r"(a[0]), "r"(a[1]), "r"(a[2]), "r"(a[3]), "r"(b[0]), "r"(b[1]));
}
__device__ __forceinline__ uint32_t packh2(float x, float y) {
    __half2 h = __floats2half2_rn(x, y);
    return *(uint32_t*)&h;
}
__device__ __forceinline__ void ldsm4(uint32_t& r0, uint32_t& r1, uint32_t& r2,
                                      uint32_t& r3, uint32_t addr) {
    asm volatile("ldmatrix.sync.aligned.m8n8.x4.shared.b16 {%0,%1,%2,%3}, [%4];"
                 : "=r"(r0), "=r"(r1), "=r"(r2), "=r"(r3) : "r"(addr));
}

static __device__ __forceinline__ void cp_async16(uint32_t dst, const void* src) {
    asm volatile("cp.async.cg.shared.global [%0], [%1], 16;" :: "r"(dst), "l"(src));
}
static __device__ __forceinline__ void cp_commit_group() {
    asm volatile("cp.async.commit_group;");
}
template <int N>
static __device__ __forceinline__ void cp_wait_group() {
    asm volatile("cp.async.wait_group %0;" :: "n"(N));
}

// ==================== merged fp32 -> fp16 conversion (5 segments) ================
__global__ __launch_bounds__(256) void cvt_all(const float* __restrict__ X,  __half* Xh,
                                               const float* __restrict__ Wq, __half* wq,
                                               const float* __restrict__ Wk, __half* wk,
                                               const float* __restrict__ Wv, __half* wv,
                                               const float* __restrict__ Wo, __half* wo) {
    const int blk = blockIdx.x;
    const float* in; __half* out; int base;
    if (blk < 8192)       { in = X;  out = Xh; base = 0; }
    else if (blk < 12288) { in = Wq; out = wq; base = 8192; }
    else if (blk < 16384) { in = Wk; out = wk; base = 12288; }
    else if (blk < 20480) { in = Wv; out = wv; base = 16384; }
    else                  { in = Wo; out = wo; base = 20480; }
    const int i = (blk - base) * 256 + threadIdx.x;
    float4 v = ((const float4*)in)[i];
    uint2 h;
    h.x = packh2(v.x, v.y);
    h.y = packh2(v.z, v.w);
    ((uint2*)out)[i] = h;
}

// ==================== coalesced V transpose (fp16): [b,h,s,dk] -> [b,h,dk,s] =====
__global__ __launch_bounds__(256) void transpose_v(const __half* __restrict__ v,
                                                   __half* __restrict__ vt) {
    __shared__ __half t[32][34];
    const int bh = blockIdx.z;
    const int s0 = blockIdx.y * 32;
    const int d0 = blockIdx.x * 32;
    const __half* src = v + (size_t)bh * SS * DK;
    __half* dst = vt + (size_t)bh * DK * SS;
    const int lx = threadIdx.x & 31, ly = threadIdx.x >> 5;
#pragma unroll
    for (int i = 0; i < 32; i += 8)
        t[ly + i][lx] = src[(size_t)(s0 + ly + i) * DK + d0 + lx];
    __syncthreads();
#pragma unroll
    for (int i = 0; i < 32; i += 8)
        dst[(size_t)(d0 + ly + i) * SS + s0 + lx] = t[lx][ly + i];
}

// ==================== FP16 GEMM: 512 threads, 64x32 warp tiles, ldmatrix =========
#define TBM 128
#define TBN 256
#define TBK 64
#define KT (DD / TBK)                        // 32
#define A_STG_B (TBM * 144)
#define B_STG_B (TBN * 144)
#define NST 4
#define STG_B (A_STG_B + B_STG_B)
#define GEMM_SMEM_BYTES (NST * STG_B)        // 221184
#define GTHREADS 512

__global__ __launch_bounds__(GTHREADS, 1) void gemm_f16(const __half* __restrict__ X,
                                                   const __half* __restrict__ W0,
                                                   const float* __restrict__ b0, void* o0,
                                                   const __half* __restrict__ W1,
                                                   const float* __restrict__ b1, void* o1,
                                                   const __half* __restrict__ W2,
                                                   const float* __restrict__ b2, void* o2,
                                                   int mode) {
    extern __shared__ __half gsm[];

    const int z = blockIdx.z;
    const __half* W   = (z == 0) ? W0 : (z == 1) ? W1 : W2;
    const float* bias = (z == 0) ? b0 : (z == 1) ? b1 : b2;
    void* out         = (z == 0) ? o0 : (z == 1) ? o1 : o2;

    const int tid  = threadIdx.x;
    const int lane = tid & 31;
    const int warp = tid >> 5;          // 0..15
    const int gid  = lane >> 2;
    const int ctid = lane & 3;
    const int mid  = lane >> 3;
    const int rowm = lane & 7;
    const int mw   = (warp >> 3) * 64;  // 0 or 64
    const int nw   = (warp & 7) * 32;   // 0..224

    const int m0 = blockIdx.y * TBM;
    const int n0 = blockIdx.x * TBN;

    const uint32_t sbase = (uint32_t)__cvta_generic_to_shared(gsm);

#define ISSUE(t) do {                                                          \
        const int s_ = (t) % NST;                                              \
        const uint32_t ab = sbase + s_ * STG_B;                                \
        const uint32_t bb = ab + A_STG_B;                                      \
        _Pragma("unroll")                                                      \
        for (int i_ = 0; i_ < 2; ++i_) {                                       \
            const int g_ = i_ * GTHREADS + tid;                                \
            const int r_ = g_ >> 3, c_ = g_ & 7;                               \
            cp_async16(ab + r_ * 144 + c_ * 16,                                \
                       X + (size_t)(m0 + r_) * DD + (t) * TBK + c_ * 8);       \
        }                                                                      \
        _Pragma("unroll")                                                      \
        for (int i_ = 0; i_ < 4; ++i_) {                                       \
            const int g_ = i_ * GTHREADS + tid;                                \
            const int r_ = g_ >> 3, c_ = g_ & 7;                               \
            cp_async16(bb + r_ * 144 + c_ * 16,                                \
                       W + (size_t)(n0 + r_) * DD + (t) * TBK + c_ * 8);       \
        }                                                                      \
        cp_commit_group();                                                     \
    } while (0)

    float acc[4][4][4];
#pragma unroll
    for (int i = 0; i < 4; ++i)
#pragma unroll
        for (int j = 0; j < 4; ++j)
#pragma unroll
            for (int r = 0; r < 4; ++r) acc[i][j][r] = 0.f;

    ISSUE(0);
    ISSUE(1);
    ISSUE(2);

    const int a_row_lane = rowm + 8 * (mid & 1);
    const int a_kb_lane  = 16 * (mid >> 1);
    const int b_row_lane = rowm + 8 * (mid >> 1);
    const int b_kb_lane  = 16 * (mid & 1);

    for (int t = 0; t < KT; ++t) {
        if (t <= KT - 3)      cp_wait_group<2>();
        else if (t == KT - 2) cp_wait_group<1>();
        else                  cp_wait_group<0>();
        __syncthreads();

        if (t + 3 < KT) ISSUE(t + 3);

        const uint32_t abase = sbase + (t % NST) * STG_B;
        const uint32_t bbase = abase + A_STG_B;

#pragma unroll
        for (int ks = 0; ks < 4; ++ks) {
            const uint32_t kb0 = ks * 32;   // bytes
            uint32_t a[4][4], b[4][2];
#pragma unroll
            for (int mt = 0; mt < 4; ++mt) {
                const int row = mw + mt * 16 + a_row_lane;
                ldsm4(a[mt][0], a[mt][1], a[mt][2], a[mt][3],
                      abase + row * 144 + kb0 + a_kb_lane);
            }
#pragma unroll
            for (int np = 0; np < 2; ++np) {
                const int row = nw + np * 16 + b_row_lane;
                ldsm4(b[2 * np][0], b[2 * np][1], b[2 * np + 1][0], b[2 * np + 1][1],
                      bbase + row * 144 + kb0 + b_kb_lane);
            }
#pragma unroll
            for (int mt = 0; mt < 4; ++mt)
#pragma unroll
                for (int nt = 0; nt < 4; ++nt)
                    mma_f16(acc[mt][nt], a[mt], b[nt]);
        }
    }

#pragma unroll
    for (int mt = 0; mt < 4; ++mt) {
#pragma unroll
        for (int nt = 0; nt < 4; ++nt) {
            const int row0 = m0 + mw + mt * 16 + gid;
            const int col  = n0 + nw + nt * 8 + ctid * 2;
            const float c0 = bias[col], c1 = bias[col + 1];
            const float e00 = acc[mt][nt][0] + c0, e01 = acc[mt][nt][1] + c1;
            const float e10 = acc[mt][nt][2] + c0, e11 = acc[mt][nt][3] + c1;
            if (mode == 0) {
                float* fo = (float*)out;
                *(float2*)&fo[(size_t)row0 * DD + col] = make_float2(e00, e01);
                *(float2*)&fo[(size_t)(row0 + 8) * DD + col] = make_float2(e10, e11);
            } else {
                __half* ho = (__half*)out;
                const int h_ = col >> 7, dk_ = col & (DK - 1);
                const int b0_ = row0 >> 11, s0_ = row0 & (SS - 1);
                const int s1_ = (row0 + 8) & (SS - 1);
                *(uint32_t*)&ho[(((size_t)(b0_ * HH + h_) * SS) + s0_) * DK + dk_] = packh2(e00, e01);
                *(uint32_t*)&ho[(((size_t)(b0_ * HH + h_) * SS) + s1_) * DK + dk_] = packh2(e10, e11);
            }
        }
    }
#undef ISSUE
}

// ==================== gate (fp32 states) ====================
__global__ __launch_bounds__(128) void gate_kernel(const float* __restrict__ X,
                                                   const float* __restrict__ Wg,
                                                   const float* __restrict__ bg,
                                                   float* __restrict__ gate) {
    __shared__ float xs[DD];
    const int m = blockIdx.x;
    for (int i = threadIdx.x * 4; i < DD; i += 128 * 4)
        *(float4*)&xs[i] = *(const float4*)&X[(size_t)m * DD + i];
    __syncthreads();

    const int w = threadIdx.x >> 5, lane = threadIdx.x & 31;
    for (int h = w; h < HH; h += 4) {
        const float* wg = &Wg[(size_t)h * DD];
        float sum = 0.f;
        for (int k = lane; k < DD; k += 32) sum += xs[k] * wg[k];
#pragma unroll
        for (int off = 16; off; off >>= 1) sum += __shfl_xor_sync(0xffffffffu, sum, off);
        if (lane == 0) {
            const float zv = sum + bg[h];
            gate[(size_t)m * HH + h] = 1.f / (1.f + __expf(-zv));
        }
    }
}

// ==================== flash attention (fp16 mma, AK=128, ldmatrix) ===============
#define AQ 128
#define AK 128
#define KROW_B 272
#define VROW_B 272
#define KSTG_B (AK * KROW_B)        // 34816 B
#define VSTG_B (DK * VROW_B)        // 34816 B
#define ATTN_SMEM_BYTES (2 * (KSTG_B + VSTG_B))   // 139264

__global__ __launch_bounds__(256, 1) void attn_mma(const __half* __restrict__ q,
                                                   const __half* __restrict__ k,
                                                   const __half* __restrict__ vT,
                                                   const float* __restrict__ gate,
                                                   __half* __restrict__ o,
                                                   const float* __restrict__ head_scale) {
    extern __shared__ __half asmh[];
    const uint32_t sK = (uint32_t)__cvta_generic_to_shared(asmh);
    const uint32_t sV = sK + 2 * KSTG_B;

    const int qb   = gridDim.x - 1 - blockIdx.x;
    const int h    = blockIdx.y;
    const int b    = blockIdx.z;
    const int tid  = threadIdx.x;
    const int lane = tid & 31;
    const int warp = tid >> 5;
    const int gid  = lane >> 2;
    const int ctid = lane & 3;
    const int mid  = lane >> 3;
    const int rowm = lane & 7;
    const float hs = head_scale[h];
    const size_t bh = ((size_t)b * HH + h) * SS;

    const __half* kptr = k + bh * DK;
    const __half* vptr = vT + (size_t)(b * HH + h) * DK * SS;

    const int rowA = qb * AQ + warp * 16 + gid;
    const int rowB = rowA + 8;

    uint32_t qa[8][4];
    {
        const uint32_t* qA = (const uint32_t*)(q + (bh + rowA) * DK);
        const uint32_t* qB = (const uint32_t*)(q + (bh + rowB) * DK);
#pragma unroll
        for (int kc = 0; kc < 8; ++kc) {
            qa[kc][0] = qA[8 * kc + ctid];
            qa[kc][1] = qB[8 * kc + ctid];
            qa[kc][2] = qA[8 * kc + ctid + 4];
            qa[kc][3] = qB[8 * kc + ctid + 4];
        }
    }

    float oacc[16][4];
#pragma unroll
    for (int nt = 0; nt < 16; ++nt)
#pragma unroll
        for (int r = 0; r < 4; ++r) oacc[nt][r] = 0.f;

    float mA = -INFINITY, mB = -INFINITY, lA = 0.f, lB = 0.f;

#define AISSUE(t) do {                                                         \
        const uint32_t kb = sK + ((t) & 1) * KSTG_B;                           \
        const uint32_t vb = sV + ((t) & 1) * VSTG_B;                           \
        _Pragma("unroll")                                                      \
        for (int i_ = 0; i_ < 8; ++i_) {                                       \
            const int g_ = i_ * 256 + tid;                                     \
            const int r_ = g_ >> 4, c_ = g_ & 15;                              \
            cp_async16(kb + r_ * KROW_B + c_ * 16,                             \
                       kptr + (size_t)((t) * AK + r_) * DK + c_ * 8);          \
        }                                                                      \
        _Pragma("unroll")                                                      \
        for (int i_ = 0; i_ < 8; ++i_) {                                       \
            const int g_ = i_ * 256 + tid;                                     \
            const int r_ = g_ >> 4, c_ = g_ & 15;                              \
            cp_async16(vb + r_ * VROW_B + c_ * 16,                             \
                       vptr + (size_t)r_ * SS + (t) * AK + c_ * 8);            \
        }                                                                      \
        cp_commit_group();                                                     \
    } while (0)

    const int ktmax = qb;
    AISSUE(0);

    const int b_row_lane = rowm + 8 * (mid >> 1);
    const int b_kb_lane  = 16 * (mid & 1);

    for (int kt = 0; kt <= ktmax; ++kt) {
        cp_wait_group<0>();
        __syncthreads();
        if (kt < ktmax) AISSUE(kt + 1);

        const uint32_t kbB = sK + (kt & 1) * KSTG_B;
        const uint32_t vbB = sV + (kt & 1) * VSTG_B;

        // ---- S = Q K^T ----
        float sacc[16][4];
#pragma unroll
        for (int nt = 0; nt < 16; ++nt)
#pragma unroll
            for (int r = 0; r < 4; ++r) sacc[nt][r] = 0.f;

#pragma unroll
        for (int kc = 0; kc < 8; ++kc) {
#pragma unroll
            for (int np = 0; np < 8; ++np) {
                uint32_t bfr[4];
                const int row = 16 * np + b_row_lane;
                ldsm4(bfr[0], bfr[1], bfr[2], bfr[3],
                      kbB + row * KROW_B + kc * 32 + b_kb_lane);
                mma_f16(sacc[2 * np],     qa[kc], bfr);
                mma_f16(sacc[2 * np + 1], qa[kc], bfr + 2);
            }
        }

        // ---- scale + ALiBi + causal ----
        const int kbase = kt * AK;
#pragma unroll
        for (int nt = 0; nt < 16; ++nt) {
            const int c0 = kbase + 8 * nt + 2 * ctid;
            const int c1 = c0 + 1;
            sacc[nt][0] = (c0 <= rowA) ? sacc[nt][0] * KEY_SCALE + (float)(c0 - rowA) * hs : -INFINITY;
            sacc[nt][1] = (c1 <= rowA) ? sacc[nt][1] * KEY_SCALE + (float)(c1 - rowA) * hs : -INFINITY;
            sacc[nt][2] = (c0 <= rowB) ? sacc[nt][2] * KEY_SCALE + (float)(c0 - rowB) * hs : -INFINITY;
            sacc[nt][3] = (c1 <= rowB) ? sacc[nt][3] * KEY_SCALE + (float)(c1 - rowB) * hs : -INFINITY;
        }

        // ---- online softmax ----
        float mxA = -INFINITY, mxB = -INFINITY;
#pragma unroll
        for (int nt = 0; nt < 16; ++nt) {
            mxA = fmaxf(mxA, fmaxf(sacc[nt][0], sacc[nt][1]));
            mxB = fmaxf(mxB, fmaxf(sacc[nt][2], sacc[nt][3]));
        }
        mxA = fmaxf(mxA, __shfl_xor_sync(0xffffffffu, mxA, 1));
        mxA = fmaxf(mxA, __shfl_xor_sync(0xffffffffu, mxA, 2));
        mxB = fmaxf(mxB, __shfl_xor_sync(0xffffffffu, mxB, 1));
        mxB = fmaxf(mxB, __shfl_xor_sync(0xffffffffu, mxB, 2));

        const float mA_new = fmaxf(mA, mxA);
        const float mB_new = fmaxf(mB, mxB);
        const float alphaA = __expf(mA - mA_new);
        const float alphaB = __expf(mB - mB_new);
        mA = mA_new; mB = mB_new;

        float rsA = 0.f, rsB = 0.f;
        uint32_t ph01[16], ph23[16];
#pragma unroll
        for (int nt = 0; nt < 16; ++nt) {
            float p0 = __expf(sacc[nt][0] - mA_new);
            float p1 = __expf(sacc[nt][1] - mA_new);
            float p2 = __expf(sacc[nt][2] - mB_new);
            float p3 = __expf(sacc[nt][3] - mB_new);
            rsA += p0 + p1;
            rsB += p2 + p3;
            ph01[nt] = packh2(p0, p1);
            ph23[nt] = packh2(p2, p3);
        }
        rsA += __shfl_xor_sync(0xffffffffu, rsA, 1);
        rsA += __shfl_xor_sync(0xffffffffu, rsA, 2);
        rsB += __shfl_xor_sync(0xffffffffu, rsB, 1);
        rsB += __shfl_xor_sync(0xffffffffu, rsB, 2);
        lA = lA * alphaA + rsA;
        lB = lB * alphaB + rsB;

        // ---- O = alpha*O + P V ----
#pragma unroll
        for (int nt = 0; nt < 16; ++nt) {
            oacc[nt][0] *= alphaA; oacc[nt][1] *= alphaA;
            oacc[nt][2] *= alphaB; oacc[nt][3] *= alphaB;
        }
#pragma unroll
        for (int kc = 0; kc < 8; ++kc) {
            uint32_t pa[4] = { ph01[2 * kc], ph23[2 * kc], ph01[2 * kc + 1], ph23[2 * kc + 1] };
#pragma unroll
            for (int np = 0; np < 8; ++np) {
                uint32_t bfr[4];
                const int row = 16 * np + b_row_lane;
                ldsm4(bfr[0], bfr[1], bfr[2], bfr[3],
                      vbB + row * VROW_B + kc * 32 + b_kb_lane);
                mma_f16(oacc[2 * np],     pa, bfr);
                mma_f16(oacc[2 * np + 1], pa, bfr + 2);
            }
        }
    }
#undef AISSUE

    const float gA = gate[((size_t)b * SS + rowA) * HH + h] / lA;
    const float gB = gate[((size_t)b * SS + rowB) * HH + h] / lB;
#pragma unroll
    for (int nt = 0; nt < 16; ++nt) {
        const int col = h * DK + 8 * nt + 2 * ctid;
        *(uint32_t*)&o[((size_t)b * SS + rowA) * DD + col] = packh2(oacc[nt][0] * gA, oacc[nt][1] * gA);
        *(uint32_t*)&o[((size_t)b * SS + rowB) * DD + col] = packh2(oacc[nt][2] * gB, oacc[nt][3] * gB);
    }
}

// ==================== launcher ====================
extern "C" void kernel_launch(void* const* d_in, const int* in_sizes, int n_in,
                              void* d_out, int out_size) {
    const float* states     = (const float*)d_in[0];
    const float* head_scale = (const float*)d_in[2];
    const float* Wq = (const float*)d_in[3];
    const float* bq = (const float*)d_in[4];
    const float* Wk = (const float*)d_in[5];
    const float* bk = (const float*)d_in[6];
    const float* Wv = (const float*)d_in[7];
    const float* bv = (const float*)d_in[8];
    const float* Wg = (const float*)d_in[9];
    const float* bg = (const float*)d_in[10];
    const float* Wo = (const float*)d_in[11];
    const float* bo = (const float*)d_in[12];

    __half *qb_, *kb_, *vb_, *vt_, *ob_, *xh, *wq, *wk, *wv, *wo;
    float *gb_;
    cudaGetSymbolAddress((void**)&qb_, g_q);
    cudaGetSymbolAddress((void**)&kb_, g_k);
    cudaGetSymbolAddress((void**)&vb_, g_v);
    cudaGetSymbolAddress((void**)&vt_, g_vt);
    cudaGetSymbolAddress((void**)&gb_, g_gate);
    cudaGetSymbolAddress((void**)&ob_, g_o);
    cudaGetSymbolAddress((void**)&xh, g_xh);
    cudaGetSymbolAddress((void**)&wq, g_wq);
    cudaGetSymbolAddress((void**)&wk, g_wk);
    cudaGetSymbolAddress((void**)&wv, g_wv);
    cudaGetSymbolAddress((void**)&wo, g_wo);

    cudaFuncSetAttribute(attn_mma, cudaFuncAttributeMaxDynamicSharedMemorySize,
                         ATTN_SMEM_BYTES);
    cudaFuncSetAttribute(gemm_f16, cudaFuncAttributeMaxDynamicSharedMemorySize,
                         GEMM_SMEM_BYTES);

    // merged fp32->fp16 conversion (states + 4 weights)
    cvt_all<<<24576, 256>>>(states, xh, Wq, wq, Wk, wk, Wv, wv, Wo, wo);

    // fused QKV projection
    dim3 qkv_grid(DD / TBN, MM / TBM, 3);   // (8, 32, 3)
    gemm_f16<<<qkv_grid, GTHREADS, GEMM_SMEM_BYTES>>>(xh,
        wq, bq, qb_, wk, bk, kb_, wv, bv, vb_, 1);

    // coalesced V transpose
    dim3 tr_grid(DK / 32, SS / 32, BB * HH);
    transpose_v<<<tr_grid, 256>>>(vb_, vt_);

    gate_kernel<<<MM, 128>>>(states, Wg, bg, gb_);

    dim3 attn_grid(SS / AQ, HH, BB);        // (16, 16, 2)
    attn_mma<<<attn_grid, 256, ATTN_SMEM_BYTES>>>(qb_, kb_, vt_, gb_, ob_, head_scale);

    // output projection (fp16 in, fp32 out)
    dim3 out_grid(DD / TBN, MM / TBM, 1);   // (8, 32, 1)
    gemm_f16<<<out_grid, GTHREADS, GEMM_SMEM_BYTES>>>(ob_,
        wo, bo, d_out, wo, bo, d_out, wo, bo, d_out, 0);
}

// round 17
// speedup vs baseline: 1.6173x; 1.6173x over previous
#include <cuda_runtime.h>
#include <cuda_fp16.h>
#include <math.h>
#include <stdint.h>

// Problem constants
#define BB 2
#define SS 2048
#define DD 2048
#define HH 16
#define DK 128
#define MM (BB*SS)          // 4096
#define KEY_SCALE 0.08838834764831843f  // 1/sqrt(128)

// -------------------- scratch (device globals; no allocations) --------------------
__device__ __half g_q[(size_t)BB*HH*SS*DK];   // [b,h,s,dk]
__device__ __half g_k[(size_t)BB*HH*SS*DK];   // [b,h,s,dk]
__device__ __half g_v[(size_t)BB*HH*SS*DK];   // [b,h,s,dk]
__device__ __half g_vt[(size_t)BB*HH*DK*SS];  // [b,h,dk,s]
__device__ float  g_gate[(size_t)BB*SS*HH];   // [b,s,h]
__device__ __half g_o[(size_t)BB*SS*DD];      // [b,s,h*dk]
__device__ __half g_xh[(size_t)MM*DD];        // states fp16
__device__ __half g_wq[(size_t)DD*DD];
__device__ __half g_wk[(size_t)DD*DD];
__device__ __half g_wv[(size_t)DD*DD];
__device__ __half g_wo[(size_t)DD*DD];

__device__ __forceinline__ void mma_f16(float* d, const uint32_t* a, const uint32_t* b) {
    asm volatile(
        "mma.sync.aligned.m16n8k16.row.col.f32.f16.f16.f32 "
        "{%0,%1,%2,%3}, {%4,%5,%6,%7}, {%8,%9}, {%0,%1,%2,%3};"
        : "+f"(d[0]), "+f"(d[1]), "+f"(d[2]), "+f"(d[3])
        : "r"(a[0]), "r"(a[1]), "r"(a[2]), "r"(a[3]), "r"(b[0]), "r"(b[1]));
}
__device__ __forceinline__ uint32_t packh2(float x, float y) {
    __half2 h = __floats2half2_rn(x, y);
    return *(uint32_t*)&h;
}
__device__ __forceinline__ void ldsm4(uint32_t& r0, uint32_t& r1, uint32_t& r2,
                                      uint32_t& r3, uint32_t addr) {
    asm volatile("ldmatrix.sync.aligned.m8n8.x4.shared.b16 {%0,%1,%2,%3}, [%4];"
                 : "=r"(r0), "=r"(r1), "=r"(r2), "=r"(r3) : "r"(addr));
}

static __device__ __forceinline__ void cp_async16(uint32_t dst, const void* src) {
    asm volatile("cp.async.cg.shared.global [%0], [%1], 16;" :: "r"(dst), "l"(src));
}
static __device__ __forceinline__ void cp_commit_group() {
    asm volatile("cp.async.commit_group;");
}
template <int N>
static __device__ __forceinline__ void cp_wait_group() {
    asm volatile("cp.async.wait_group %0;" :: "n"(N));
}

// ==================== merged fp32 -> fp16 conversion (5 segments) ================
__global__ __launch_bounds__(256) void cvt_all(const float* __restrict__ X,  __half* Xh,
                                               const float* __restrict__ Wq, __half* wq,
                                               const float* __restrict__ Wk, __half* wk,
                                               const float* __restrict__ Wv, __half* wv,
                                               const float* __restrict__ Wo, __half* wo) {
    const int blk = blockIdx.x;
    const float* in; __half* out; int base;
    if (blk < 8192)       { in = X;  out = Xh; base = 0; }
    else if (blk < 12288) { in = Wq; out = wq; base = 8192; }
    else if (blk < 16384) { in = Wk; out = wk; base = 12288; }
    else if (blk < 20480) { in = Wv; out = wv; base = 16384; }
    else                  { in = Wo; out = wo; base = 20480; }
    const int i = (blk - base) * 256 + threadIdx.x;
    float4 v = ((const float4*)in)[i];
    uint2 h;
    h.x = packh2(v.x, v.y);
    h.y = packh2(v.z, v.w);
    ((uint2*)out)[i] = h;
}

// ==================== coalesced V transpose (fp16): [b,h,s,dk] -> [b,h,dk,s] =====
__global__ __launch_bounds__(256) void transpose_v(const __half* __restrict__ v,
                                                   __half* __restrict__ vt) {
    __shared__ __half t[32][34];
    const int bh = blockIdx.z;
    const int s0 = blockIdx.y * 32;
    const int d0 = blockIdx.x * 32;
    const __half* src = v + (size_t)bh * SS * DK;
    __half* dst = vt + (size_t)bh * DK * SS;
    const int lx = threadIdx.x & 31, ly = threadIdx.x >> 5;
#pragma unroll
    for (int i = 0; i < 32; i += 8)
        t[ly + i][lx] = src[(size_t)(s0 + ly + i) * DK + d0 + lx];
    __syncthreads();
#pragma unroll
    for (int i = 0; i < 32; i += 8)
        dst[(size_t)(d0 + ly + i) * SS + s0 + lx] = t[lx][ly + i];
}

// ==================== FP16 GEMM: 128x128 CTA, 3-stage, 2 CTAs/SM, ldmatrix =======
#define TBM 128
#define TBN 128
#define TBK 64
#define KT (DD / TBK)                        // 32
#define A_STG_B (TBM * 144)                  // 18432 B
#define B_STG_B (TBN * 144)                  // 18432 B
#define NST 3
#define STG_B (A_STG_B + B_STG_B)            // 36864 B
#define GEMM_SMEM_BYTES (NST * STG_B)        // 110592 B -> 2 CTAs/SM

__global__ __launch_bounds__(256, 2) void gemm_f16(const __half* __restrict__ X,
                                                   const __half* __restrict__ W0,
                                                   const float* __restrict__ b0, void* o0,
                                                   const __half* __restrict__ W1,
                                                   const float* __restrict__ b1, void* o1,
                                                   const __half* __restrict__ W2,
                                                   const float* __restrict__ b2, void* o2,
                                                   int mode) {
    extern __shared__ __half gsm[];

    const int z = blockIdx.z;
    const __half* W   = (z == 0) ? W0 : (z == 1) ? W1 : W2;
    const float* bias = (z == 0) ? b0 : (z == 1) ? b1 : b2;
    void* out         = (z == 0) ? o0 : (z == 1) ? o1 : o2;

    const int tid  = threadIdx.x;
    const int lane = tid & 31;
    const int warp = tid >> 5;          // 0..7
    const int gid  = lane >> 2;
    const int ctid = lane & 3;
    const int mid  = lane >> 3;
    const int rowm = lane & 7;
    const int mw   = (warp >> 2) * 64;  // 0 or 64
    const int nw   = (warp & 3) * 32;   // 0,32,64,96

    const int m0 = blockIdx.y * TBM;
    const int n0 = blockIdx.x * TBN;

    const uint32_t sbase = (uint32_t)__cvta_generic_to_shared(gsm);

#define ISSUE(t) do {                                                          \
        const int s_ = (t) % NST;                                              \
        const uint32_t ab = sbase + s_ * STG_B;                                \
        const uint32_t bb = ab + A_STG_B;                                      \
        _Pragma("unroll")                                                      \
        for (int i_ = 0; i_ < 4; ++i_) {                                       \
            const int g_ = i_ * 256 + tid;                                     \
            const int r_ = g_ >> 3, c_ = g_ & 7;                               \
            cp_async16(ab + r_ * 144 + c_ * 16,                                \
                       X + (size_t)(m0 + r_) * DD + (t) * TBK + c_ * 8);       \
        }                                                                      \
        _Pragma("unroll")                                                      \
        for (int i_ = 0; i_ < 4; ++i_) {                                       \
            const int g_ = i_ * 256 + tid;                                     \
            const int r_ = g_ >> 3, c_ = g_ & 7;                               \
            cp_async16(bb + r_ * 144 + c_ * 16,                                \
                       W + (size_t)(n0 + r_) * DD + (t) * TBK + c_ * 8);       \
        }                                                                      \
        cp_commit_group();                                                     \
    } while (0)

    float acc[4][4][4];
#pragma unroll
    for (int i = 0; i < 4; ++i)
#pragma unroll
        for (int j = 0; j < 4; ++j)
#pragma unroll
            for (int r = 0; r < 4; ++r) acc[i][j][r] = 0.f;

    ISSUE(0);
    ISSUE(1);

    const int a_row_lane = rowm + 8 * (mid & 1);
    const int a_kb_lane  = 16 * (mid >> 1);
    const int b_row_lane = rowm + 8 * (mid >> 1);
    const int b_kb_lane  = 16 * (mid & 1);

    for (int t = 0; t < KT; ++t) {
        if (t < KT - 1) cp_wait_group<1>();
        else            cp_wait_group<0>();
        __syncthreads();

        if (t + 2 < KT) ISSUE(t + 2);

        const uint32_t abase = sbase + (t % NST) * STG_B;
        const uint32_t bbase = abase + A_STG_B;

#pragma unroll
        for (int ks = 0; ks < 4; ++ks) {
            const uint32_t kb0 = ks * 32;   // bytes
            uint32_t a[4][4], b[4][2];
#pragma unroll
            for (int mt = 0; mt < 4; ++mt) {
                const int row = mw + mt * 16 + a_row_lane;
                ldsm4(a[mt][0], a[mt][1], a[mt][2], a[mt][3],
                      abase + row * 144 + kb0 + a_kb_lane);
            }
#pragma unroll
            for (int np = 0; np < 2; ++np) {
                const int row = nw + np * 16 + b_row_lane;
                ldsm4(b[2 * np][0], b[2 * np][1], b[2 * np + 1][0], b[2 * np + 1][1],
                      bbase + row * 144 + kb0 + b_kb_lane);
            }
#pragma unroll
            for (int mt = 0; mt < 4; ++mt)
#pragma unroll
                for (int nt = 0; nt < 4; ++nt)
                    mma_f16(acc[mt][nt], a[mt], b[nt]);
        }
    }

#pragma unroll
    for (int mt = 0; mt < 4; ++mt) {
#pragma unroll
        for (int nt = 0; nt < 4; ++nt) {
            const int row0 = m0 + mw + mt * 16 + gid;
            const int col  = n0 + nw + nt * 8 + ctid * 2;
            const float c0 = bias[col], c1 = bias[col + 1];
            const float e00 = acc[mt][nt][0] + c0, e01 = acc[mt][nt][1] + c1;
            const float e10 = acc[mt][nt][2] + c0, e11 = acc[mt][nt][3] + c1;
            if (mode == 0) {
                float* fo = (float*)out;
                *(float2*)&fo[(size_t)row0 * DD + col] = make_float2(e00, e01);
                *(float2*)&fo[(size_t)(row0 + 8) * DD + col] = make_float2(e10, e11);
            } else {
                __half* ho = (__half*)out;
                const int h_ = col >> 7, dk_ = col & (DK - 1);
                const int b0_ = row0 >> 11, s0_ = row0 & (SS - 1);
                const int s1_ = (row0 + 8) & (SS - 1);
                *(uint32_t*)&ho[(((size_t)(b0_ * HH + h_) * SS) + s0_) * DK + dk_] = packh2(e00, e01);
                *(uint32_t*)&ho[(((size_t)(b0_ * HH + h_) * SS) + s1_) * DK + dk_] = packh2(e10, e11);
            }
        }
    }
#undef ISSUE
}

// ==================== gate (fp32 states) ====================
__global__ __launch_bounds__(128) void gate_kernel(const float* __restrict__ X,
                                                   const float* __restrict__ Wg,
                                                   const float* __restrict__ bg,
                                                   float* __restrict__ gate) {
    __shared__ float xs[DD];
    const int m = blockIdx.x;
    for (int i = threadIdx.x * 4; i < DD; i += 128 * 4)
        *(float4*)&xs[i] = *(const float4*)&X[(size_t)m * DD + i];
    __syncthreads();

    const int w = threadIdx.x >> 5, lane = threadIdx.x & 31;
    for (int h = w; h < HH; h += 4) {
        const float* wg = &Wg[(size_t)h * DD];
        float sum = 0.f;
        for (int k = lane; k < DD; k += 32) sum += xs[k] * wg[k];
#pragma unroll
        for (int off = 16; off; off >>= 1) sum += __shfl_xor_sync(0xffffffffu, sum, off);
        if (lane == 0) {
            const float zv = sum + bg[h];
            gate[(size_t)m * HH + h] = 1.f / (1.f + __expf(-zv));
        }
    }
}

// ==================== flash attention (fp16 mma, AK=128, ldmatrix) ===============
#define AQ 128
#define AK 128
#define KROW_B 272
#define VROW_B 272
#define KSTG_B (AK * KROW_B)        // 34816 B
#define VSTG_B (DK * VROW_B)        // 34816 B
#define ATTN_SMEM_BYTES (2 * (KSTG_B + VSTG_B))   // 139264

__global__ __launch_bounds__(256, 1) void attn_mma(const __half* __restrict__ q,
                                                   const __half* __restrict__ k,
                                                   const __half* __restrict__ vT,
                                                   const float* __restrict__ gate,
                                                   __half* __restrict__ o,
                                                   const float* __restrict__ head_scale) {
    extern __shared__ __half asmh[];
    const uint32_t sK = (uint32_t)__cvta_generic_to_shared(asmh);
    const uint32_t sV = sK + 2 * KSTG_B;

    const int qb   = gridDim.x - 1 - blockIdx.x;
    const int h    = blockIdx.y;
    const int b    = blockIdx.z;
    const int tid  = threadIdx.x;
    const int lane = tid & 31;
    const int warp = tid >> 5;
    const int gid  = lane >> 2;
    const int ctid = lane & 3;
    const int mid  = lane >> 3;
    const int rowm = lane & 7;
    const float hs = head_scale[h];
    const size_t bh = ((size_t)b * HH + h) * SS;

    const __half* kptr = k + bh * DK;
    const __half* vptr = vT + (size_t)(b * HH + h) * DK * SS;

    const int rowA = qb * AQ + warp * 16 + gid;
    const int rowB = rowA + 8;

    uint32_t qa[8][4];
    {
        const uint32_t* qA = (const uint32_t*)(q + (bh + rowA) * DK);
        const uint32_t* qB = (const uint32_t*)(q + (bh + rowB) * DK);
#pragma unroll
        for (int kc = 0; kc < 8; ++kc) {
            qa[kc][0] = qA[8 * kc + ctid];
            qa[kc][1] = qB[8 * kc + ctid];
            qa[kc][2] = qA[8 * kc + ctid + 4];
            qa[kc][3] = qB[8 * kc + ctid + 4];
        }
    }

    float oacc[16][4];
#pragma unroll
    for (int nt = 0; nt < 16; ++nt)
#pragma unroll
        for (int r = 0; r < 4; ++r) oacc[nt][r] = 0.f;

    float mA = -INFINITY, mB = -INFINITY, lA = 0.f, lB = 0.f;

#define AISSUE(t) do {                                                         \
        const uint32_t kb = sK + ((t) & 1) * KSTG_B;                           \
        const uint32_t vb = sV + ((t) & 1) * VSTG_B;                           \
        _Pragma("unroll")                                                      \
        for (int i_ = 0; i_ < 8; ++i_) {                                       \
            const int g_ = i_ * 256 + tid;                                     \
            const int r_ = g_ >> 4, c_ = g_ & 15;                              \
            cp_async16(kb + r_ * KROW_B + c_ * 16,                             \
                       kptr + (size_t)((t) * AK + r_) * DK + c_ * 8);          \
        }                                                                      \
        _Pragma("unroll")                                                      \
        for (int i_ = 0; i_ < 8; ++i_) {                                       \
            const int g_ = i_ * 256 + tid;                                     \
            const int r_ = g_ >> 4, c_ = g_ & 15;                              \
            cp_async16(vb + r_ * VROW_B + c_ * 16,                             \
                       vptr + (size_t)r_ * SS + (t) * AK + c_ * 8);            \
        }                                                                      \
        cp_commit_group();                                                     \
    } while (0)

    const int ktmax = qb;
    AISSUE(0);

    const int b_row_lane = rowm + 8 * (mid >> 1);
    const int b_kb_lane  = 16 * (mid & 1);

    for (int kt = 0; kt <= ktmax; ++kt) {
        cp_wait_group<0>();
        __syncthreads();
        if (kt < ktmax) AISSUE(kt + 1);

        const uint32_t kbB = sK + (kt & 1) * KSTG_B;
        const uint32_t vbB = sV + (kt & 1) * VSTG_B;

        // ---- S = Q K^T ----
        float sacc[16][4];
#pragma unroll
        for (int nt = 0; nt < 16; ++nt)
#pragma unroll
            for (int r = 0; r < 4; ++r) sacc[nt][r] = 0.f;

#pragma unroll
        for (int kc = 0; kc < 8; ++kc) {
#pragma unroll
            for (int np = 0; np < 8; ++np) {
                uint32_t bfr[4];
                const int row = 16 * np + b_row_lane;
                ldsm4(bfr[0], bfr[1], bfr[2], bfr[3],
                      kbB + row * KROW_B + kc * 32 + b_kb_lane);
                mma_f16(sacc[2 * np],     qa[kc], bfr);
                mma_f16(sacc[2 * np + 1], qa[kc], bfr + 2);
            }
        }

        // ---- scale + ALiBi + causal ----
        const int kbase = kt * AK;
#pragma unroll
        for (int nt = 0; nt < 16; ++nt) {
            const int c0 = kbase + 8 * nt + 2 * ctid;
            const int c1 = c0 + 1;
            sacc[nt][0] = (c0 <= rowA) ? sacc[nt][0] * KEY_SCALE + (float)(c0 - rowA) * hs : -INFINITY;
            sacc[nt][1] = (c1 <= rowA) ? sacc[nt][1] * KEY_SCALE + (float)(c1 - rowA) * hs : -INFINITY;
            sacc[nt][2] = (c0 <= rowB) ? sacc[nt][2] * KEY_SCALE + (float)(c0 - rowB) * hs : -INFINITY;
            sacc[nt][3] = (c1 <= rowB) ? sacc[nt][3] * KEY_SCALE + (float)(c1 - rowB) * hs : -INFINITY;
        }

        // ---- online softmax ----
        float mxA = -INFINITY, mxB = -INFINITY;
#pragma unroll
        for (int nt = 0; nt < 16; ++nt) {
            mxA = fmaxf(mxA, fmaxf(sacc[nt][0], sacc[nt][1]));
            mxB = fmaxf(mxB, fmaxf(sacc[nt][2], sacc[nt][3]));
        }
        mxA = fmaxf(mxA, __shfl_xor_sync(0xffffffffu, mxA, 1));
        mxA = fmaxf(mxA, __shfl_xor_sync(0xffffffffu, mxA, 2));
        mxB = fmaxf(mxB, __shfl_xor_sync(0xffffffffu, mxB, 1));
        mxB = fmaxf(mxB, __shfl_xor_sync(0xffffffffu, mxB, 2));

        const float mA_new = fmaxf(mA, mxA);
        const float mB_new = fmaxf(mB, mxB);
        const float alphaA = __expf(mA - mA_new);
        const float alphaB = __expf(mB - mB_new);
        mA = mA_new; mB = mB_new;

        float rsA = 0.f, rsB = 0.f;
        uint32_t ph01[16], ph23[16];
#pragma unroll
        for (int nt = 0; nt < 16; ++nt) {
            float p0 = __expf(sacc[nt][0] - mA_new);
            float p1 = __expf(sacc[nt][1] - mA_new);
            float p2 = __expf(sacc[nt][2] - mB_new);
            float p3 = __expf(sacc[nt][3] - mB_new);
            rsA += p0 + p1;
            rsB += p2 + p3;
            ph01[nt] = packh2(p0, p1);
            ph23[nt] = packh2(p2, p3);
        }
        rsA += __shfl_xor_sync(0xffffffffu, rsA, 1);
        rsA += __shfl_xor_sync(0xffffffffu, rsA, 2);
        rsB += __shfl_xor_sync(0xffffffffu, rsB, 1);
        rsB += __shfl_xor_sync(0xffffffffu, rsB, 2);
        lA = lA * alphaA + rsA;
        lB = lB * alphaB + rsB;

        // ---- O = alpha*O + P V ----
#pragma unroll
        for (int nt = 0; nt < 16; ++nt) {
            oacc[nt][0] *= alphaA; oacc[nt][1] *= alphaA;
            oacc[nt][2] *= alphaB; oacc[nt][3] *= alphaB;
        }
#pragma unroll
        for (int kc = 0; kc < 8; ++kc) {
            uint32_t pa[4] = { ph01[2 * kc], ph23[2 * kc], ph01[2 * kc + 1], ph23[2 * kc + 1] };
#pragma unroll
            for (int np = 0; np < 8; ++np) {
                uint32_t bfr[4];
                const int row = 16 * np + b_row_lane;
                ldsm4(bfr[0], bfr[1], bfr[2], bfr[3],
                      vbB + row * VROW_B + kc * 32 + b_kb_lane);
                mma_f16(oacc[2 * np],     pa, bfr);
                mma_f16(oacc[2 * np + 1], pa, bfr + 2);
            }
        }
    }
#undef AISSUE

    const float gA = gate[((size_t)b * SS + rowA) * HH + h] / lA;
    const float gB = gate[((size_t)b * SS + rowB) * HH + h] / lB;
#pragma unroll
    for (int nt = 0; nt < 16; ++nt) {
        const int col = h * DK + 8 * nt + 2 * ctid;
        *(uint32_t*)&o[((size_t)b * SS + rowA) * DD + col] = packh2(oacc[nt][0] * gA, oacc[nt][1] * gA);
        *(uint32_t*)&o[((size_t)b * SS + rowB) * DD + col] = packh2(oacc[nt][2] * gB, oacc[nt][3] * gB);
    }
}

// ==================== launcher ====================
extern "C" void kernel_launch(void* const* d_in, const int* in_sizes, int n_in,
                              void* d_out, int out_size) {
    const float* states     = (const float*)d_in[0];
    const float* head_scale = (const float*)d_in[2];
    const float* Wq = (const float*)d_in[3];
    const float* bq = (const float*)d_in[4];
    const float* Wk = (const float*)d_in[5];
    const float* bk = (const float*)d_in[6];
    const float* Wv = (const float*)d_in[7];
    const float* bv = (const float*)d_in[8];
    const float* Wg = (const float*)d_in[9];
    const float* bg = (const float*)d_in[10];
    const float* Wo = (const float*)d_in[11];
    const float* bo = (const float*)d_in[12];

    __half *qb_, *kb_, *vb_, *vt_, *ob_, *xh, *wq, *wk, *wv, *wo;
    float *gb_;
    cudaGetSymbolAddress((void**)&qb_, g_q);
    cudaGetSymbolAddress((void**)&kb_, g_k);
    cudaGetSymbolAddress((void**)&vb_, g_v);
    cudaGetSymbolAddress((void**)&vt_, g_vt);
    cudaGetSymbolAddress((void**)&gb_, g_gate);
    cudaGetSymbolAddress((void**)&ob_, g_o);
    cudaGetSymbolAddress((void**)&xh, g_xh);
    cudaGetSymbolAddress((void**)&wq, g_wq);
    cudaGetSymbolAddress((void**)&wk, g_wk);
    cudaGetSymbolAddress((void**)&wv, g_wv);
    cudaGetSymbolAddress((void**)&wo, g_wo);

    cudaFuncSetAttribute(attn_mma, cudaFuncAttributeMaxDynamicSharedMemorySize,
                         ATTN_SMEM_BYTES);
    cudaFuncSetAttribute(gemm_f16, cudaFuncAttributeMaxDynamicSharedMemorySize,
                         GEMM_SMEM_BYTES);

    // merged fp32->fp16 conversion (states + 4 weights)
    cvt_all<<<24576, 256>>>(states, xh, Wq, wq, Wk, wk, Wv, wv, Wo, wo);

    // fused QKV projection
    dim3 qkv_grid(DD / TBN, MM / TBM, 3);   // (16, 32, 3)
    gemm_f16<<<qkv_grid, 256, GEMM_SMEM_BYTES>>>(xh,
        wq, bq, qb_, wk, bk, kb_, wv, bv, vb_, 1);

    // coalesced V transpose
    dim3 tr_grid(DK / 32, SS / 32, BB * HH);
    transpose_v<<<tr_grid, 256>>>(vb_, vt_);

    gate_kernel<<<MM, 128>>>(states, Wg, bg, gb_);

    dim3 attn_grid(SS / AQ, HH, BB);        // (16, 16, 2)
    attn_mma<<<attn_grid, 256, ATTN_SMEM_BYTES>>>(qb_, kb_, vt_, gb_, ob_, head_scale);

    // output projection (fp16 in, fp32 out)
    dim3 out_grid(DD / TBN, MM / TBM, 1);   // (16, 32, 1)
    gemm_f16<<<out_grid, 256, GEMM_SMEM_BYTES>>>(ob_,
        wo, bo, d_out, wo, bo, d_out, wo, bo, d_out, 0);
}